// round 15
// baseline (speedup 1.0000x reference)
#include <cuda_runtime.h>
#include <cuda_bf16.h>
#include <math.h>
#include <float.h>
#include <stdint.h>

// ---------------------------------------------------------------------------
// Problem constants
// ---------------------------------------------------------------------------
#define B        4
#define N        2048
#define DIM      512
#define HEADS    8
#define DHEAD    64
#define INNER    512
#define ROWS     (B*N)
#define NARROW_K 9
#define WIDE_K   9
#define WIDE_DIL 5

// ---------------------------------------------------------------------------
// Device scratch (fp32 only)
// ---------------------------------------------------------------------------
__device__ __align__(16) float g_qkv[ROWS * 3 * INNER];
__device__ __align__(16) float g_qs [ROWS * INNER];
__device__ __align__(16) float g_ks [ROWS * INNER];
__device__ __align__(16) float g_vm [ROWS * INNER];
__device__ __align__(16) float g_ctx_part[B*HEADS*8*DHEAD*DHEAD];
__device__ __align__(16) float g_ctx[B*HEADS*DHEAD*DHEAD];
__device__ __align__(16) float g_attn[ROWS * INNER];
__device__ __align__(16) float g_tok [ROWS * DIM];
__device__ __align__(16) float g_xm  [ROWS * DIM];
__device__ __align__(16) float g_cn  [ROWS * DIM];   // narrow conv raw
__device__ __align__(16) float g_cw  [ROWS * DIM];   // wide conv raw
__device__ __align__(16) float g_ln1 [ROWS * DIM];
__device__ __align__(16) float g_ff  [ROWS * DIM];
__device__ __align__(16) float g_wkn [NARROW_K*DIM*DIM];  // [k][ci][co]
__device__ __align__(16) float g_wkw [WIDE_K*DIM*DIM];
__device__ __align__(16) int   g_mask[ROWS];

// ---------------------------------------------------------------------------
// Helpers
// ---------------------------------------------------------------------------
__device__ __forceinline__ float gelu_exact(float x) {
    return 0.5f * x * (1.0f + erff(x * 0.7071067811865476f));
}
__device__ __forceinline__ unsigned long long pack2(float x, float y) {
    unsigned long long r;
    asm("mov.b64 %0, {%1, %2};" : "=l"(r) : "f"(x), "f"(y));
    return r;
}
__device__ __forceinline__ void fma2(unsigned long long &d,
                                     unsigned long long a,
                                     unsigned long long b) {
    asm("fma.rn.f32x2 %0, %1, %2, %0;" : "+l"(d) : "l"(a), "l"(b));
}
__device__ __forceinline__ float2 unpack2(unsigned long long v) {
    float2 r;
    asm("mov.b64 {%0, %1}, %2;" : "=f"(r.x), "=f"(r.y) : "l"(v));
    return r;
}

// ---------------------------------------------------------------------------
// Mask normalization
// ---------------------------------------------------------------------------
__global__ void mask_prep_kernel(const unsigned char* raw) {
    __shared__ int is_bool;
    if (threadIdx.x == 0) is_bool = 0;
    __syncthreads();
    for (int p = threadIdx.x; p < ROWS; p += blockDim.x)
        if ((p & 3) && raw[p]) is_bool = 1;
    __syncthreads();
    const int* as_int = (const int*)raw;
    for (int i = threadIdx.x; i < ROWS; i += blockDim.x)
        g_mask[i] = is_bool ? (raw[i] != 0) : (as_int[i] != 0);
}

// ---------------------------------------------------------------------------
// 128x128 SGEMM, K-step 16, f32x2 FMA, register prefetch (proven R13).
// ---------------------------------------------------------------------------
__global__ __launch_bounds__(256, 2)
void sgemm16_kernel(const float* __restrict__ A,
                    const float* __restrict__ Bm,
                    const float* __restrict__ bias,
                    float* __restrict__ C,
                    float* __restrict__ C2masked,
                    int M, int Nn, int K, int do_gelu) {
    __shared__ float As[16][132];
    __shared__ float Bs[16][128];
    const int n0 = blockIdx.x * 128;
    const int m0 = blockIdx.y * 128;
    const int tid = threadIdx.x;
    const int tx = tid & 15, ty = tid >> 4;

    const int arow = tid >> 2;
    const int akq  = (tid & 3) * 4;
    const int bkk = tid >> 5;
    const int bnq = (tid & 31) * 4;

    const float* Aptr0 = A + (size_t)(m0 + arow) * K + akq;
    const float* Aptr1 = A + (size_t)(m0 + arow + 64) * K + akq;
    const float* Bptr0 = Bm + (size_t)bkk * Nn + n0 + bnq;
    const float* Bptr1 = Bm + (size_t)(bkk + 8) * Nn + n0 + bnq;

    float4 ar0 = *(const float4*)Aptr0;
    float4 ar1 = *(const float4*)Aptr1;
    float4 br0 = *(const float4*)Bptr0;
    float4 br1 = *(const float4*)Bptr1;

    unsigned long long acc[8][4];
#pragma unroll
    for (int i = 0; i < 8; i++)
#pragma unroll
        for (int j = 0; j < 4; j++) acc[i][j] = 0ull;

    const int nsteps = K >> 4;
    for (int s = 0; s < nsteps; s++) {
        As[akq + 0][arow] = ar0.x;  As[akq + 1][arow] = ar0.y;
        As[akq + 2][arow] = ar0.z;  As[akq + 3][arow] = ar0.w;
        As[akq + 0][arow + 64] = ar1.x;  As[akq + 1][arow + 64] = ar1.y;
        As[akq + 2][arow + 64] = ar1.z;  As[akq + 3][arow + 64] = ar1.w;
        *(float4*)&Bs[bkk][bnq] = br0;
        *(float4*)&Bs[bkk + 8][bnq] = br1;
        __syncthreads();
        if (s + 1 < nsteps) {
            ar0 = *(const float4*)(Aptr0 + (s + 1) * 16);
            ar1 = *(const float4*)(Aptr1 + (s + 1) * 16);
            br0 = *(const float4*)(Bptr0 + (size_t)(s + 1) * 16 * Nn);
            br1 = *(const float4*)(Bptr1 + (size_t)(s + 1) * 16 * Nn);
        }
#pragma unroll
        for (int kk = 0; kk < 16; kk++) {
            float4 a0 = *(float4*)&As[kk][ty * 4];
            float4 a1 = *(float4*)&As[kk][ty * 4 + 64];
            ulonglong2 b0 = *(ulonglong2*)&Bs[kk][tx * 4];
            ulonglong2 b1 = *(ulonglong2*)&Bs[kk][tx * 4 + 64];
            unsigned long long bb[4] = {b0.x, b0.y, b1.x, b1.y};
            unsigned long long av[8];
            av[0] = pack2(a0.x, a0.x); av[1] = pack2(a0.y, a0.y);
            av[2] = pack2(a0.z, a0.z); av[3] = pack2(a0.w, a0.w);
            av[4] = pack2(a1.x, a1.x); av[5] = pack2(a1.y, a1.y);
            av[6] = pack2(a1.z, a1.z); av[7] = pack2(a1.w, a1.w);
#pragma unroll
            for (int i = 0; i < 8; i++)
#pragma unroll
                for (int j = 0; j < 4; j++) fma2(acc[i][j], av[i], bb[j]);
        }
        __syncthreads();
    }

#pragma unroll
    for (int i = 0; i < 8; i++) {
        int row = m0 + ty * 4 + (i & 3) + ((i >= 4) ? 64 : 0);
        float mk = C2masked ? (g_mask[row] ? 1.0f : 0.0f) : 0.0f;
#pragma unroll
        for (int half = 0; half < 2; half++) {
            int col = n0 + tx * 4 + half * 64;
            float2 v0 = unpack2(acc[i][half * 2 + 0]);
            float2 v1 = unpack2(acc[i][half * 2 + 1]);
            float4 v = make_float4(v0.x, v0.y, v1.x, v1.y);
            if (bias) {
                v.x += bias[col]; v.y += bias[col + 1];
                v.z += bias[col + 2]; v.w += bias[col + 3];
            }
            if (do_gelu) {
                v.x = gelu_exact(v.x); v.y = gelu_exact(v.y);
                v.z = gelu_exact(v.z); v.w = gelu_exact(v.w);
            }
            *(float4*)&C[(size_t)row * Nn + col] = v;
            if (C2masked) {
                float4 vm = make_float4(v.x * mk, v.y * mk, v.z * mk, v.w * mk);
                *(float4*)&C2masked[(size_t)row * Nn + col] = vm;
            }
        }
    }
}

// ---------------------------------------------------------------------------
// q softmax (+rope, *0.125) and masked v
// ---------------------------------------------------------------------------
__global__ void q_v_kernel() {
    const int row = blockIdx.x;
    const int pos = row & (N - 1);
    const int tid = threadIdx.x;
    const int w = tid >> 5;
    const int l = tid & 31;

    float inv = expf(-(float)(2 * l) * (1.0f / 64.0f) * logf(10000.0f));
    float arg = (float)pos * inv;
    const float* qrow = g_qkv + (size_t)row * (3 * INNER);
    float x1 = qrow[w * 64 + l]      + sinf(arg);
    float x2 = qrow[w * 64 + l + 32] + cosf(arg);
    float m = fmaxf(x1, x2);
#pragma unroll
    for (int o = 16; o > 0; o >>= 1) m = fmaxf(m, __shfl_xor_sync(0xffffffffu, m, o));
    float e1 = expf(x1 - m), e2 = expf(x2 - m);
    float s = e1 + e2;
#pragma unroll
    for (int o = 16; o > 0; o >>= 1) s += __shfl_xor_sync(0xffffffffu, s, o);
    float r = 0.125f / s;
    g_qs[(size_t)row * INNER + w * 64 + l]      = e1 * r;
    g_qs[(size_t)row * INNER + w * 64 + l + 32] = e2 * r;

    float mk = g_mask[row] ? 1.0f : 0.0f;
    for (int i = tid; i < INNER; i += 256)
        g_vm[(size_t)row * INNER + i] = mk * qrow[2 * INNER + i];
}

// ---------------------------------------------------------------------------
// k column softmax over sequence axis
// ---------------------------------------------------------------------------
__global__ void k_colsoftmax_kernel() {
    const int col = blockIdx.x;
    const int b = blockIdx.y;
    const int d = col & 63;
    const int tid = threadIdx.x;
    __shared__ float red[256];

    int i_ = (d < 32) ? d : (d - 32);
    float inv = expf(-(float)(2 * i_) * (1.0f / 64.0f) * logf(10000.0f));
    bool use_sin = (d < 32);

    float vals[8];
    float mx = -FLT_MAX;
#pragma unroll
    for (int j = 0; j < 8; j++) {
        int n = tid + 256 * j;
        int row = b * N + n;
        float arg = (float)n * inv;
        float rope = use_sin ? sinf(arg) : cosf(arg);
        float v = g_qkv[(size_t)row * (3 * INNER) + INNER + col] + rope;
        v = g_mask[row] ? v : -FLT_MAX;
        vals[j] = v;
        mx = fmaxf(mx, v);
    }
    red[tid] = mx; __syncthreads();
    for (int o = 128; o > 0; o >>= 1) {
        if (tid < o) red[tid] = fmaxf(red[tid], red[tid + o]);
        __syncthreads();
    }
    mx = red[0]; __syncthreads();

    float s = 0.f;
    float ev[8];
#pragma unroll
    for (int j = 0; j < 8; j++) {
        ev[j] = (vals[j] == -FLT_MAX) ? 0.f : expf(vals[j] - mx);
        s += ev[j];
    }
    red[tid] = s; __syncthreads();
    for (int o = 128; o > 0; o >>= 1) {
        if (tid < o) red[tid] += red[tid + o];
        __syncthreads();
    }
    float rs = 1.0f / red[0];
#pragma unroll
    for (int j = 0; j < 8; j++) {
        int n = tid + 256 * j;
        g_ks[(size_t)(b * N + n) * INNER + col] = ev[j] * rs;
    }
}

// ---------------------------------------------------------------------------
// context partial + reduce
// ---------------------------------------------------------------------------
__global__ void ctx_partial_kernel() {
    const int bh = blockIdx.x;
    const int split = blockIdx.y;
    const int b = bh >> 3, h = bh & 7;
    const int tid = threadIdx.x;
    const int ty = tid >> 4, tx = tid & 15;
    __shared__ float Ks[16][64];
    __shared__ float Vs[16][64];

    float acc[4][4];
#pragma unroll
    for (int i = 0; i < 4; i++)
#pragma unroll
        for (int j = 0; j < 4; j++) acc[i][j] = 0.f;

    const int n0 = split * 256;
    for (int c = 0; c < 16; c++) {
        int nb = n0 + c * 16;
        int r = tid >> 6, colc = tid & 63;
#pragma unroll
        for (int i = 0; i < 4; i++) {
            int rr = r + 4 * i;
            size_t base = (size_t)(b * N + nb + rr) * INNER + h * 64 + colc;
            Ks[rr][colc] = g_ks[base];
            Vs[rr][colc] = g_vm[base];
        }
        __syncthreads();
#pragma unroll
        for (int kk = 0; kk < 16; kk++) {
            float a[4], bb[4];
#pragma unroll
            for (int i = 0; i < 4; i++) a[i] = Ks[kk][ty * 4 + i];
#pragma unroll
            for (int j = 0; j < 4; j++) bb[j] = Vs[kk][tx * 4 + j];
#pragma unroll
            for (int i = 0; i < 4; i++)
#pragma unroll
                for (int j = 0; j < 4; j++) acc[i][j] = fmaf(a[i], bb[j], acc[i][j]);
        }
        __syncthreads();
    }
    float* dst = g_ctx_part + (size_t)(bh * 8 + split) * 4096;
#pragma unroll
    for (int i = 0; i < 4; i++)
#pragma unroll
        for (int j = 0; j < 4; j++)
            dst[(ty * 4 + i) * 64 + tx * 4 + j] = acc[i][j];
}

__global__ void ctx_reduce_kernel() {
    int i = blockIdx.x * blockDim.x + threadIdx.x;
    if (i >= B * HEADS * 4096) return;
    int bh = i >> 12, pos = i & 4095;
    float s = 0.f;
#pragma unroll
    for (int sp = 0; sp < 8; sp++) s += g_ctx_part[(size_t)(bh * 8 + sp) * 4096 + pos];
    g_ctx[i] = s;
}

// ---------------------------------------------------------------------------
// apply context to q
// ---------------------------------------------------------------------------
__global__ void attn_apply_kernel() {
    const int blk = blockIdx.x;
    const int tile = blk & 63;
    const int h = (blk >> 6) & 7;
    const int b = blk >> 9;
    const int t0 = tile * 32;
    const int tid = threadIdx.x;
    __shared__ float ctx_sh[64 * 65];
    __shared__ float qs_sh[32 * 64];

    const float* ctxp = g_ctx + (size_t)(b * 8 + h) * 4096;
#pragma unroll
    for (int i = 0; i < 16; i++) {
        int idx = tid + 256 * i;
        ctx_sh[(idx >> 6) * 65 + (idx & 63)] = ctxp[idx];
    }
#pragma unroll
    for (int i = 0; i < 8; i++) {
        int idx = tid + 256 * i;
        int tok = idx >> 6, d = idx & 63;
        qs_sh[idx] = g_qs[(size_t)(b * N + t0 + tok) * INNER + h * 64 + d];
    }
    __syncthreads();
#pragma unroll
    for (int o = 0; o < 8; o++) {
        int idx = tid + 256 * o;
        int tok = idx >> 6, e = idx & 63;
        float s = 0.f;
#pragma unroll
        for (int d = 0; d < 64; d++)
            s = fmaf(qs_sh[tok * 64 + d], ctx_sh[d * 65 + e], s);
        g_attn[(size_t)(b * N + t0 + tok) * INNER + h * 64 + e] = s;
    }
}

// ---------------------------------------------------------------------------
// conv weight transpose: w[co][ci][k] -> wk[k][ci][co]
// ---------------------------------------------------------------------------
__global__ void wtrans_kernel(const float* __restrict__ w, float* __restrict__ wk, int Kt) {
    int idx = blockIdx.x * blockDim.x + threadIdx.x;
    int total = DIM * DIM * Kt;
    if (idx >= total) return;
    int co = idx / (DIM * Kt);
    int r = idx - co * (DIM * Kt);
    int ci = r / Kt;
    int k = r - ci * Kt;
    wk[((size_t)k * DIM + ci) * DIM + co] = w[idx];
}

// ---------------------------------------------------------------------------
// MERGED conv1d, tile 128(t) x 64(co): 1024 blocks for fine-grained wave
// packing. Thread tile 8x4. Body is the proven engine with halved N-tile.
// grid: (co_tiles=8, t_tiles=16, 8) — z = b + 4*which.
// ---------------------------------------------------------------------------
__global__ __launch_bounds__(256, 2)
void conv64_kernel(const float* __restrict__ wkn,
                   const float* __restrict__ wkw,
                   float* __restrict__ outn,
                   float* __restrict__ outw) {
    const int zz = blockIdx.z;
    const int b = zz & 3;
    const int which = zz >> 2;
    const float* __restrict__ wk = which ? wkw : wkn;
    float* __restrict__ out = which ? outw : outn;
    const int dil = which ? WIDE_DIL : 1;

    __shared__ float Xs[16][132];
    __shared__ float Ws[16][64];
    const int co0 = blockIdx.x * 64;
    const int t0 = blockIdx.y * 128;
    const int tid = threadIdx.x;
    const int tx = tid & 15, ty = tid >> 4;

    const int arow = tid >> 2;          // 0..63
    const int akq  = (tid & 3) * 4;
    const int wkk = tid >> 4;           // 0..15
    const int wnq = (tid & 15) * 4;     // 0..60

    unsigned long long acc[8][2];
#pragma unroll
    for (int i = 0; i < 8; i++) {
        acc[i][0] = 0ull; acc[i][1] = 0ull;
    }

    const int total = 9 * 32;   // taps * (512/16)

    float4 ar0, ar1, wr;
    {
        const int shift = (0 - 4) * dil;
        int tt0 = t0 + arow + shift;
        int tt1 = tt0 + 64;
        ar0 = make_float4(0.f, 0.f, 0.f, 0.f);
        ar1 = ar0;
        if (tt0 >= 0 && tt0 < N)
            ar0 = *(const float4*)&g_xm[(size_t)(b * N + tt0) * DIM + akq];
        if (tt1 >= 0 && tt1 < N)
            ar1 = *(const float4*)&g_xm[(size_t)(b * N + tt1) * DIM + akq];
        wr = *(const float4*)&wk[(size_t)wkk * DIM + co0 + wnq];
    }

    for (int s = 0; s < total; s++) {
        Xs[akq + 0][arow] = ar0.x;  Xs[akq + 1][arow] = ar0.y;
        Xs[akq + 2][arow] = ar0.z;  Xs[akq + 3][arow] = ar0.w;
        Xs[akq + 0][arow + 64] = ar1.x;  Xs[akq + 1][arow + 64] = ar1.y;
        Xs[akq + 2][arow + 64] = ar1.z;  Xs[akq + 3][arow + 64] = ar1.w;
        *(float4*)&Ws[wkk][wnq] = wr;
        __syncthreads();
        if (s + 1 < total) {
            const int s2 = s + 1;
            const int k2 = s2 >> 5;
            const int ci2 = (s2 & 31) * 16;
            const int shift = (k2 - 4) * dil;
            int tt0 = t0 + arow + shift;
            int tt1 = tt0 + 64;
            ar0 = make_float4(0.f, 0.f, 0.f, 0.f);
            ar1 = ar0;
            if (tt0 >= 0 && tt0 < N)
                ar0 = *(const float4*)&g_xm[(size_t)(b * N + tt0) * DIM + ci2 + akq];
            if (tt1 >= 0 && tt1 < N)
                ar1 = *(const float4*)&g_xm[(size_t)(b * N + tt1) * DIM + ci2 + akq];
            wr = *(const float4*)&wk[((size_t)k2 * DIM + ci2 + wkk) * DIM + co0 + wnq];
        }
#pragma unroll
        for (int kk = 0; kk < 16; kk++) {
            float4 a0 = *(float4*)&Xs[kk][ty * 4];
            float4 a1 = *(float4*)&Xs[kk][ty * 4 + 64];
            ulonglong2 b2 = *(ulonglong2*)&Ws[kk][tx * 4];
            unsigned long long av[8];
            av[0] = pack2(a0.x, a0.x); av[1] = pack2(a0.y, a0.y);
            av[2] = pack2(a0.z, a0.z); av[3] = pack2(a0.w, a0.w);
            av[4] = pack2(a1.x, a1.x); av[5] = pack2(a1.y, a1.y);
            av[6] = pack2(a1.z, a1.z); av[7] = pack2(a1.w, a1.w);
#pragma unroll
            for (int i = 0; i < 8; i++) {
                fma2(acc[i][0], av[i], b2.x);
                fma2(acc[i][1], av[i], b2.y);
            }
        }
        __syncthreads();
    }

#pragma unroll
    for (int i = 0; i < 8; i++) {
        int t = t0 + ty * 4 + (i & 3) + ((i >= 4) ? 64 : 0);
        int co = co0 + tx * 4;
        size_t idx = (size_t)(b * N + t) * DIM + co;
        float2 v0 = unpack2(acc[i][0]);
        float2 v1 = unpack2(acc[i][1]);
        *(float4*)&out[idx] = make_float4(v0.x, v0.y, v1.x, v1.y);
    }
}

// ---------------------------------------------------------------------------
// ln1: v = tok + gelu(cn + bn) + gelu(cw + bw); LN -> g_ln1
// ---------------------------------------------------------------------------
__global__ void ln1_fused_kernel(const float* __restrict__ bn,
                                 const float* __restrict__ bw,
                                 const float* __restrict__ g,
                                 const float* __restrict__ bvec) {
    const int row = blockIdx.x;
    const int tid = threadIdx.x;
    __shared__ float red[256];
    size_t base = (size_t)row * DIM;
    float v0 = g_tok[base + tid]
             + gelu_exact(g_cn[base + tid] + bn[tid])
             + gelu_exact(g_cw[base + tid] + bw[tid]);
    float v1 = g_tok[base + tid + 256]
             + gelu_exact(g_cn[base + tid + 256] + bn[tid + 256])
             + gelu_exact(g_cw[base + tid + 256] + bw[tid + 256]);
    red[tid] = v0 + v1; __syncthreads();
    for (int o = 128; o > 0; o >>= 1) {
        if (tid < o) red[tid] += red[tid + o];
        __syncthreads();
    }
    float mean = red[0] * (1.0f / DIM); __syncthreads();
    float d0 = v0 - mean, d1 = v1 - mean;
    red[tid] = d0 * d0 + d1 * d1; __syncthreads();
    for (int o = 128; o > 0; o >>= 1) {
        if (tid < o) red[tid] += red[tid + o];
        __syncthreads();
    }
    float var = red[0] * (1.0f / DIM);
    float rstd = rsqrtf(var + 1e-5f);
    g_ln1[base + tid]       = d0 * rstd * g[tid] + bvec[tid];
    g_ln1[base + tid + 256] = d1 * rstd * g[tid + 256] + bvec[tid + 256];
}

// ---------------------------------------------------------------------------
// ln2 (plain) -> output
// ---------------------------------------------------------------------------
__global__ void ln2_kernel(const float* __restrict__ x,
                           const float* __restrict__ g,
                           const float* __restrict__ bvec,
                           float* __restrict__ out) {
    const int row = blockIdx.x;
    const int tid = threadIdx.x;
    __shared__ float red[256];
    float v0 = x[(size_t)row * DIM + tid];
    float v1 = x[(size_t)row * DIM + tid + 256];
    red[tid] = v0 + v1; __syncthreads();
    for (int o = 128; o > 0; o >>= 1) {
        if (tid < o) red[tid] += red[tid + o];
        __syncthreads();
    }
    float mean = red[0] * (1.0f / DIM); __syncthreads();
    float d0 = v0 - mean, d1 = v1 - mean;
    red[tid] = d0 * d0 + d1 * d1; __syncthreads();
    for (int o = 128; o > 0; o >>= 1) {
        if (tid < o) red[tid] += red[tid + o];
        __syncthreads();
    }
    float var = red[0] * (1.0f / DIM);
    float rstd = rsqrtf(var + 1e-5f);
    out[(size_t)row * DIM + tid]       = d0 * rstd * g[tid] + bvec[tid];
    out[(size_t)row * DIM + tid + 256] = d1 * rstd * g[tid + 256] + bvec[tid + 256];
}

// ---------------------------------------------------------------------------
// Launch
// ---------------------------------------------------------------------------
extern "C" void kernel_launch(void* const* d_in, const int* in_sizes, int n_in,
                              void* d_out, int out_size) {
    const float* tokens   = (const float*)d_in[0];
    const unsigned char* mask_raw = (const unsigned char*)d_in[1];
    const float* w_qkv    = (const float*)d_in[2];
    const float* w_out    = (const float*)d_in[3];
    const float* b_out    = (const float*)d_in[4];
    const float* w_narrow = (const float*)d_in[5];
    const float* b_narrow = (const float*)d_in[6];
    const float* w_wide   = (const float*)d_in[7];
    const float* b_wide   = (const float*)d_in[8];
    const float* ln1_g    = (const float*)d_in[9];
    const float* ln1_b    = (const float*)d_in[10];
    const float* ff_w     = (const float*)d_in[11];
    const float* ff_b     = (const float*)d_in[12];
    const float* ln2_g    = (const float*)d_in[13];
    const float* ln2_b    = (const float*)d_in[14];
    float* outp = (float*)d_out;

    float *p_qkv, *p_attn, *p_tok, *p_xm, *p_cn, *p_cw, *p_ln1, *p_ff, *p_wkn, *p_wkw;
    cudaGetSymbolAddress((void**)&p_qkv, g_qkv);
    cudaGetSymbolAddress((void**)&p_attn, g_attn);
    cudaGetSymbolAddress((void**)&p_tok, g_tok);
    cudaGetSymbolAddress((void**)&p_xm,  g_xm);
    cudaGetSymbolAddress((void**)&p_cn,  g_cn);
    cudaGetSymbolAddress((void**)&p_cw,  g_cw);
    cudaGetSymbolAddress((void**)&p_ln1, g_ln1);
    cudaGetSymbolAddress((void**)&p_ff,  g_ff);
    cudaGetSymbolAddress((void**)&p_wkn, g_wkn);
    cudaGetSymbolAddress((void**)&p_wkw, g_wkw);

    // 1. mask
    mask_prep_kernel<<<1, 256>>>(mask_raw);

    // 2. qkv GEMM (8192 x 1536 x 512)
    sgemm16_kernel<<<dim3(3 * INNER / 128, ROWS / 128), 256>>>(
        tokens, w_qkv, nullptr, p_qkv, nullptr, ROWS, 3 * INNER, DIM, 0);

    // 3. attention small kernels
    q_v_kernel<<<ROWS, 256>>>();
    k_colsoftmax_kernel<<<dim3(INNER, B), 256>>>();
    ctx_partial_kernel<<<dim3(B * HEADS, 8), 256>>>();
    ctx_reduce_kernel<<<(B * HEADS * 4096 + 255) / 256, 256>>>();
    attn_apply_kernel<<<B * HEADS * (N / 32), 256>>>();

    // 4. out projection (+bias) with fused masked store for conv input
    sgemm16_kernel<<<dim3(DIM / 128, ROWS / 128), 256>>>(
        p_attn, w_out, b_out, p_tok, p_xm, ROWS, DIM, INNER, 0);

    // 5. conv weight transposes
    wtrans_kernel<<<(DIM * DIM * NARROW_K + 255) / 256, 256>>>(w_narrow, p_wkn, NARROW_K);
    wtrans_kernel<<<(DIM * DIM * WIDE_K + 255) / 256, 256>>>(w_wide, p_wkw, WIDE_K);

    // 6. BOTH convs in one launch, 128x64 tiles (1024 blocks — fine packing)
    conv64_kernel<<<dim3(DIM / 64, N / 128, 2 * B), 256>>>(
        p_wkn, p_wkw, p_cn, p_cw);

    // 7. ln1 (residual + gelu(conv+bias) fused)
    ln1_fused_kernel<<<ROWS, 256>>>(b_narrow, b_wide, ln1_g, ln1_b);

    // 8. ff GEMM + bias + gelu
    sgemm16_kernel<<<dim3(DIM / 128, ROWS / 128), 256>>>(
        p_ln1, ff_w, ff_b, p_ff, nullptr, ROWS, DIM, DIM, 1);

    // 9. ln2 -> output
    ln2_kernel<<<ROWS, 256>>>(p_ff, ln2_g, ln2_b, outp);
}